// round 1
// baseline (speedup 1.0000x reference)
#include <cuda_runtime.h>

#define NA 8400      // anchors / preds per batch
#define NG 2048      // bs*M = 16*128 flattened gts
#define BS 16
#define M  128
#define GT_TILE 32
#define TPB 256

// ---------------------------------------------------------------------------
// Kernel 1: distances (2048 x 8400) + gious (2048 x 8400), fused.
// One thread = one anchor column. 32 gt boxes staged in smem per block.
// ---------------------------------------------------------------------------
__global__ __launch_bounds__(TPB)
void dist_giou_kernel(const float4* __restrict__ gt,      // [2048]
                      const float4* __restrict__ anc,     // [8400]
                      float* __restrict__ dist,           // [2048*8400]
                      float* __restrict__ giou)           // [2048*8400]
{
    __shared__ float4 sgt[GT_TILE];
    const int a  = blockIdx.x * TPB + threadIdx.x;
    const int g0 = blockIdx.y * GT_TILE;

    if (threadIdx.x < GT_TILE) sgt[threadIdx.x] = gt[g0 + threadIdx.x];
    __syncthreads();

    if (a >= NA) return;

    const float4 ab = anc[a];
    const float acx   = 0.5f * (ab.x + ab.z);
    const float acy   = 0.5f * (ab.y + ab.w);
    const float area2 = (ab.z - ab.x) * (ab.w - ab.y);

    #pragma unroll 8
    for (int k = 0; k < GT_TILE; k++) {
        const float4 gb = sgt[k];
        const long idx = (long)(g0 + k) * NA + a;

        // --- distance between centers ---
        const float gcx = 0.5f * (gb.x + gb.z);
        const float gcy = 0.5f * (gb.y + gb.w);
        const float dx = gcx - acx, dy = gcy - acy;
        __stcs(&dist[idx], sqrtf(dx * dx + dy * dy));

        // --- GIoU ---
        const float area1 = (gb.z - gb.x) * (gb.w - gb.y);
        const float ltx = fmaxf(gb.x, ab.x), lty = fmaxf(gb.y, ab.y);
        const float rbx = fminf(gb.z, ab.z), rby = fminf(gb.w, ab.w);
        const float w = fmaxf(rbx - ltx, 0.0f), h = fmaxf(rby - lty, 0.0f);
        const float overlap = w * h;
        const float uni = fmaxf(area1 + area2 - overlap, 1e-6f);
        const float iou = overlap / uni;

        const float eltx = fminf(gb.x, ab.x), elty = fminf(gb.y, ab.y);
        const float erbx = fmaxf(gb.z, ab.z), erby = fmaxf(gb.w, ab.w);
        const float ew = fmaxf(erbx - eltx, 0.0f), eh = fmaxf(erby - elty, 0.0f);
        const float enc = fmaxf(ew * eh, 1e-6f);

        __stcs(&giou[idx], iou - (enc - uni) / enc);
    }
}

// ---------------------------------------------------------------------------
// Kernel 2: overlaps (16 x 128 x 8400), plain IoU gt-vs-pred per batch.
// One thread = one pred column of a batch; 32 gt boxes in smem per block.
// ---------------------------------------------------------------------------
__global__ __launch_bounds__(TPB)
void iou_kernel(const float4* __restrict__ gt,     // [16*128]
                const float4* __restrict__ pred,   // [16*8400]
                float* __restrict__ out)           // [16*128*8400]
{
    __shared__ float4 sgt[GT_TILE];
    const int b  = blockIdx.z;
    const int a  = blockIdx.x * TPB + threadIdx.x;
    const int m0 = blockIdx.y * GT_TILE;

    if (threadIdx.x < GT_TILE) sgt[threadIdx.x] = gt[b * M + m0 + threadIdx.x];
    __syncthreads();

    if (a >= NA) return;

    const float4 pb = pred[b * NA + a];
    const float area2 = (pb.z - pb.x) * (pb.w - pb.y);

    #pragma unroll 8
    for (int k = 0; k < GT_TILE; k++) {
        const float4 gb = sgt[k];
        const float area1 = (gb.z - gb.x) * (gb.w - gb.y);
        const float ltx = fmaxf(gb.x, pb.x), lty = fmaxf(gb.y, pb.y);
        const float rbx = fminf(gb.z, pb.z), rby = fminf(gb.w, pb.w);
        const float w = fmaxf(rbx - ltx, 0.0f), h = fmaxf(rby - lty, 0.0f);
        const float overlap = w * h;
        const float uni = area1 + area2 - overlap + 1e-9f;

        const long idx = ((long)b * M + (m0 + k)) * NA + a;
        __stcs(&out[idx], overlap / uni);
    }
}

extern "C" void kernel_launch(void* const* d_in, const int* in_sizes, int n_in,
                              void* d_out, int out_size)
{
    const float4* gt   = (const float4*)d_in[0];  // (16,128,4)
    const float4* pred = (const float4*)d_in[1];  // (16,8400,4)
    const float4* anc  = (const float4*)d_in[2];  // (8400,4)

    float* dist = (float*)d_out;                            // 2048*8400
    float* ovlp = dist + (long)NG * NA;                     // 16*128*8400
    float* giou = ovlp + (long)BS * M * NA;                 // 2048*8400

    const int ablocks = (NA + TPB - 1) / TPB;  // 33

    dim3 g1(ablocks, NG / GT_TILE);            // 33 x 64
    dist_giou_kernel<<<g1, TPB>>>(gt, anc, dist, giou);

    dim3 g2(ablocks, M / GT_TILE, BS);         // 33 x 4 x 16
    iou_kernel<<<g2, TPB>>>(gt, pred, ovlp);
}

// round 2
// speedup vs baseline: 2.2162x; 2.2162x over previous
#include <cuda_runtime.h>

#define NA 8400      // anchors / preds per batch
#define NC (NA/2)    // float2 columns = 4200
#define NG 2048      // bs*M flattened gts
#define BS 16
#define M  128
#define GT_TILE 32
#define TPB 256

__device__ __forceinline__ float fdiv_ap(float a, float b) {
    float r; asm("div.approx.f32 %0, %1, %2;" : "=f"(r) : "f"(a), "f"(b)); return r;
}
__device__ __forceinline__ float fsqrt_ap(float a) {
    float r; asm("sqrt.approx.f32 %0, %1;" : "=f"(r) : "f"(a)); return r;
}

// ---------------------------------------------------------------------------
// Kernel 1: distances + gious, fused. 2 anchors per thread, 32 gts per block.
// ---------------------------------------------------------------------------
__global__ __launch_bounds__(TPB)
void dist_giou_kernel(const float4* __restrict__ gt,
                      const float4* __restrict__ anc,
                      float* __restrict__ dist,
                      float* __restrict__ giou)
{
    __shared__ float4 sgt[GT_TILE];
    const int c  = blockIdx.x * TPB + threadIdx.x;   // float2 column
    const int g0 = blockIdx.y * GT_TILE;

    if (threadIdx.x < GT_TILE) sgt[threadIdx.x] = gt[g0 + threadIdx.x];
    __syncthreads();

    if (c >= NC) return;
    const int a = 2 * c;

    const float4 A0 = anc[a];
    const float4 A1 = anc[a + 1];
    const float acx0 = 0.5f * (A0.x + A0.z), acy0 = 0.5f * (A0.y + A0.w);
    const float acx1 = 0.5f * (A1.x + A1.z), acy1 = 0.5f * (A1.y + A1.w);
    const float ar0  = (A0.z - A0.x) * (A0.w - A0.y);
    const float ar1  = (A1.z - A1.x) * (A1.w - A1.y);

    float* pd = dist + (long)g0 * NA + a;
    float* pg = giou + (long)g0 * NA + a;

    #pragma unroll 8
    for (int k = 0; k < GT_TILE; k++) {
        const float4 gb = sgt[k];
        const float gcx   = 0.5f * (gb.x + gb.z);
        const float gcy   = 0.5f * (gb.y + gb.w);
        const float area1 = (gb.z - gb.x) * (gb.w - gb.y);

        // distances
        float dx0 = gcx - acx0, dy0 = gcy - acy0;
        float dx1 = gcx - acx1, dy1 = gcy - acy1;
        float2 dv = make_float2(fsqrt_ap(dx0 * dx0 + dy0 * dy0),
                                fsqrt_ap(dx1 * dx1 + dy1 * dy1));
        __stcs((float2*)pd, dv);

        // giou, anchor 0
        float w0 = fmaxf(fminf(gb.z, A0.z) - fmaxf(gb.x, A0.x), 0.0f);
        float h0 = fmaxf(fminf(gb.w, A0.w) - fmaxf(gb.y, A0.y), 0.0f);
        float ov0  = w0 * h0;
        float uni0 = area1 + ar0 - ov0;                    // >= 16 >> eps
        float ew0  = fmaxf(gb.z, A0.z) - fminf(gb.x, A0.x);
        float eh0  = fmaxf(gb.w, A0.w) - fminf(gb.y, A0.y);
        float g_0  = fdiv_ap(ov0, uni0) - 1.0f + fdiv_ap(uni0, ew0 * eh0);

        // giou, anchor 1
        float w1 = fmaxf(fminf(gb.z, A1.z) - fmaxf(gb.x, A1.x), 0.0f);
        float h1 = fmaxf(fminf(gb.w, A1.w) - fmaxf(gb.y, A1.y), 0.0f);
        float ov1  = w1 * h1;
        float uni1 = area1 + ar1 - ov1;
        float ew1  = fmaxf(gb.z, A1.z) - fminf(gb.x, A1.x);
        float eh1  = fmaxf(gb.w, A1.w) - fminf(gb.y, A1.y);
        float g_1  = fdiv_ap(ov1, uni1) - 1.0f + fdiv_ap(uni1, ew1 * eh1);

        __stcs((float2*)pg, make_float2(g_0, g_1));

        pd += NA; pg += NA;
    }
}

// ---------------------------------------------------------------------------
// Kernel 2: overlaps (16 x 128 x 8400), IoU gt-vs-pred. 2 preds per thread.
// ---------------------------------------------------------------------------
__global__ __launch_bounds__(TPB)
void iou_kernel(const float4* __restrict__ gt,
                const float4* __restrict__ pred,
                float* __restrict__ out)
{
    __shared__ float4 sgt[GT_TILE];
    const int b  = blockIdx.z;
    const int c  = blockIdx.x * TPB + threadIdx.x;
    const int m0 = blockIdx.y * GT_TILE;

    if (threadIdx.x < GT_TILE) sgt[threadIdx.x] = gt[b * M + m0 + threadIdx.x];
    __syncthreads();

    if (c >= NC) return;
    const int a = 2 * c;

    const float4 P0 = pred[b * NA + a];
    const float4 P1 = pred[b * NA + a + 1];
    const float ar0 = (P0.z - P0.x) * (P0.w - P0.y);
    const float ar1 = (P1.z - P1.x) * (P1.w - P1.y);

    float* po = out + ((long)b * M + m0) * NA + a;

    #pragma unroll 8
    for (int k = 0; k < GT_TILE; k++) {
        const float4 gb = sgt[k];
        const float area1 = (gb.z - gb.x) * (gb.w - gb.y);

        float w0 = fmaxf(fminf(gb.z, P0.z) - fmaxf(gb.x, P0.x), 0.0f);
        float h0 = fmaxf(fminf(gb.w, P0.w) - fmaxf(gb.y, P0.y), 0.0f);
        float ov0 = w0 * h0;
        float r0  = fdiv_ap(ov0, area1 + ar0 - ov0 + 1e-9f);

        float w1 = fmaxf(fminf(gb.z, P1.z) - fmaxf(gb.x, P1.x), 0.0f);
        float h1 = fmaxf(fminf(gb.w, P1.w) - fmaxf(gb.y, P1.y), 0.0f);
        float ov1 = w1 * h1;
        float r1  = fdiv_ap(ov1, area1 + ar1 - ov1 + 1e-9f);

        __stcs((float2*)po, make_float2(r0, r1));
        po += NA;
    }
}

extern "C" void kernel_launch(void* const* d_in, const int* in_sizes, int n_in,
                              void* d_out, int out_size)
{
    const float4* gt   = (const float4*)d_in[0];
    const float4* pred = (const float4*)d_in[1];
    const float4* anc  = (const float4*)d_in[2];

    float* dist = (float*)d_out;
    float* ovlp = dist + (long)NG * NA;
    float* giou = ovlp + (long)BS * M * NA;

    const int cblocks = (NC + TPB - 1) / TPB;   // 17

    dim3 g1(cblocks, NG / GT_TILE);             // 17 x 64
    dist_giou_kernel<<<g1, TPB>>>(gt, anc, dist, giou);

    dim3 g2(cblocks, M / GT_TILE, BS);          // 17 x 4 x 16
    iou_kernel<<<g2, TPB>>>(gt, pred, ovlp);
}